// round 7
// baseline (speedup 1.0000x reference)
#include <cuda_runtime.h>
#include <cstdint>

// Q = L @ L^T, L lower-triangular 3x3 from packed [a,b,c,d,e,f]:
//   Q00=a*a  Q01=a*b      Q02=a*d
//   Q10=a*b  Q11=b*b+c*c  Q12=b*d+c*e
//   Q20=a*d  Q21=b*d+c*e  Q22=d*d+e*e+f*f
//
// Warp-autonomous 3-tile pipeline. Each of the 4 warps owns a self-contained
// slice (64 rows/tile: 96 input f4, 144 output f4, contiguous, warp-aligned)
// so only __syncwarp is needed. All 3 tiles' input loads are issued up-front
// via cp.async.cg (9 outstanding 16B copies per lane, 3 commit groups), then
// tiles are computed/stored as their groups drain (wait_group 2 -> 1 -> 0).
// Missing tiles at the grid tail use empty commit groups so wait counts stay
// compile-time constants.

#define TPB 128
#define ROWS_PB 256
#define IN_F4 (ROWS_PB * 6 / 4)    // 384 f4/tile ; per warp: 96 (3/lane)
#define OUT_F4 (ROWS_PB * 9 / 4)   // 576 f4/tile ; per warp: 144 (4.5/lane)
#define W_IN 96
#define W_OUT 144
#define W_ROWS 64
#define TILES_PB 3

__device__ __forceinline__ void cp_async16(uint32_t saddr, const void* gaddr) {
    asm volatile("cp.async.cg.shared.global [%0], [%1], 16;\n" :: "r"(saddr), "l"(gaddr));
}
__device__ __forceinline__ void cp_commit() {
    asm volatile("cp.async.commit_group;\n" ::: "memory");
}
template <int N>
__device__ __forceinline__ void cp_wait() {
    asm volatile("cp.async.wait_group %0;\n" :: "n"(N) : "memory");
}

__device__ __forceinline__ void row_to_q(const float* __restrict__ v, float* __restrict__ o) {
    const float a = v[0], b = v[1], c = v[2], d = v[3], e = v[4], f = v[5];
    const float ab = a * b;
    const float ad = a * d;
    const float bdce = fmaf(b, d, c * e);
    o[0] = a * a;
    o[1] = ab;
    o[2] = ad;
    o[3] = ab;
    o[4] = fmaf(b, b, c * c);
    o[5] = bdce;
    o[6] = ad;
    o[7] = bdce;
    o[8] = fmaf(d, d, fmaf(e, e, f * f));
}

// Compute this warp's 64 rows of one tile: smem input slice -> smem output slice.
__device__ __forceinline__ void warp_compute(const float* __restrict__ sin_w,
                                             float* __restrict__ sout_w, int l)
{
#pragma unroll
    for (int j = 0; j < 2; j++) {
        const int r = l + 32 * j;
        float v[6], o[9];
#pragma unroll
        for (int k = 0; k < 6; k++) v[k] = sin_w[r * 6 + k];
        row_to_q(v, o);
#pragma unroll
        for (int k = 0; k < 9; k++) sout_w[r * 9 + k] = o[k];
    }
}

// Store this warp's 144 output float4 (dense, warp-coalesced, evict-first).
__device__ __forceinline__ void warp_store(float4* __restrict__ op_w,
                                           const float* __restrict__ sout_w, int l)
{
    const float4* so4 = reinterpret_cast<const float4*>(sout_w);
#pragma unroll
    for (int k = 0; k < 4; k++)
        __stcs(op_w + l + 32 * k, so4[l + 32 * k]);
    if (l < W_OUT - 128)  // remaining 16 float4
        __stcs(op_w + l + 128, so4[l + 128]);
}

__global__ __launch_bounds__(TPB) void chol_to_cov_warp3(const float4* __restrict__ in4,
                                                         float4* __restrict__ out4,
                                                         int num_tiles)
{
    __shared__ float4 s_in[TILES_PB][IN_F4];  // 18 KB
    __shared__ float  s_out[ROWS_PB * 9];     // 9 KB (warp-private slices, reused)

    const int t = threadIdx.x;
    const int w = t >> 5;
    const int l = t & 31;

    const int tile0 = blockIdx.x * TILES_PB;

    // Issue this warp's input slice for up to 3 tiles; one commit group per
    // tile slot (empty groups for missing tiles complete immediately).
#pragma unroll
    for (int i = 0; i < TILES_PB; i++) {
        if (tile0 + i < num_tiles) {
            const float4* ip = in4 + (size_t)(tile0 + i) * IN_F4 + w * W_IN;
            uint32_t sb = (uint32_t)__cvta_generic_to_shared(&s_in[i][w * W_IN]);
#pragma unroll
            for (int k = 0; k < 3; k++)
                cp_async16(sb + (l + 32 * k) * 16u, ip + l + 32 * k);
        }
        cp_commit();
    }

    float* sout_w = s_out + w * W_ROWS * 9;

    // ---- Tile 0 ----
    cp_wait<2>();
    __syncwarp();
    warp_compute(reinterpret_cast<const float*>(&s_in[0][w * W_IN]), sout_w, l);
    __syncwarp();
    warp_store(out4 + (size_t)tile0 * OUT_F4 + w * W_OUT, sout_w, l);

    // ---- Tile 1 ----
    if (tile0 + 1 < num_tiles) {
        cp_wait<1>();
        __syncwarp();   // tile1 input visible; tile0 store LDS issued in-order before this
        warp_compute(reinterpret_cast<const float*>(&s_in[1][w * W_IN]), sout_w, l);
        __syncwarp();
        warp_store(out4 + (size_t)(tile0 + 1) * OUT_F4 + w * W_OUT, sout_w, l);
    }

    // ---- Tile 2 ----
    if (tile0 + 2 < num_tiles) {
        cp_wait<0>();
        __syncwarp();
        warp_compute(reinterpret_cast<const float*>(&s_in[2][w * W_IN]), sout_w, l);
        __syncwarp();
        warp_store(out4 + (size_t)(tile0 + 2) * OUT_F4 + w * W_OUT, sout_w, l);
    }
}

// Scalar tail for the (< ROWS_PB) remainder rows.
__global__ void chol_to_cov_tail(const float* __restrict__ in,
                                 float* __restrict__ out,
                                 int start_row, int n_rows)
{
    const int r = start_row + blockIdx.x * blockDim.x + threadIdx.x;
    if (r >= n_rows) return;
    float v[6], o[9];
#pragma unroll
    for (int k = 0; k < 6; k++) v[k] = in[(size_t)r * 6 + k];
    row_to_q(v, o);
#pragma unroll
    for (int k = 0; k < 9; k++) out[(size_t)r * 9 + k] = o[k];
}

extern "C" void kernel_launch(void* const* d_in, const int* in_sizes, int n_in,
                              void* d_out, int out_size)
{
    const float* in = (const float*)d_in[0];
    float* out = (float*)d_out;
    const int n_rows = in_sizes[0] / 6;

    const int num_tiles = n_rows / ROWS_PB;
    if (num_tiles > 0) {
        const int blocks = (num_tiles + TILES_PB - 1) / TILES_PB;
        chol_to_cov_warp3<<<blocks, TPB>>>((const float4*)in, (float4*)out, num_tiles);
    }
    const int done = num_tiles * ROWS_PB;
    if (done < n_rows) {
        const int rem = n_rows - done;
        chol_to_cov_tail<<<(rem + 127) / 128, 128>>>(in, out, done, n_rows);
    }
}

// round 8
// speedup vs baseline: 1.0070x; 1.0070x over previous
#include <cuda_runtime.h>
#include <cstdint>

// Q = L @ L^T, L lower-triangular 3x3 from packed [a,b,c,d,e,f]:
//   Q00=a*a  Q01=a*b      Q02=a*d
//   Q10=a*b  Q11=b*b+c*c  Q12=b*d+c*e
//   Q20=a*d  Q21=b*d+c*e  Q22=d*d+e*e+f*f
//
// Warp-autonomous 2-tile pipeline with ASYNC BULK STORES.
// Loads: cp.async.cg per lane (3x16B per tile), 2 commit groups (as R6).
// Stores: each warp's 2304B contiguous output slice is written to smem and
// then shipped by ONE cp.async.bulk.global.shared::cta issued by the elected
// lane (bulk_group). Output smem is double-buffered so the warp never waits
// on its own store drain; the async engine overlaps store writeback with the
// next blocks' loads.

#define TPB 128
#define ROWS_PB 256
#define IN_F4 (ROWS_PB * 6 / 4)    // 384 f4/tile ; per warp: 96 (3/lane)
#define OUT_F4 (ROWS_PB * 9 / 4)   // 576 f4/tile ; per warp: 144
#define W_IN 96
#define W_ROWS 64
#define W_OUT_FLOATS (W_ROWS * 9)  // 576 floats = 2304 bytes
#define W_OUT_BYTES 2304

__device__ __forceinline__ void cp_async16(uint32_t saddr, const void* gaddr) {
    asm volatile("cp.async.cg.shared.global [%0], [%1], 16;\n" :: "r"(saddr), "l"(gaddr));
}
__device__ __forceinline__ void cp_commit() {
    asm volatile("cp.async.commit_group;\n" ::: "memory");
}
template <int N>
__device__ __forceinline__ void cp_wait() {
    asm volatile("cp.async.wait_group %0;\n" :: "n"(N) : "memory");
}

// Async bulk store: smem (shared::cta) -> gmem, tracked by bulk groups.
__device__ __forceinline__ void bulk_store(void* gaddr, uint32_t saddr, uint32_t bytes) {
    asm volatile("cp.async.bulk.global.shared::cta.bulk_group [%0], [%1], %2;\n"
                 :: "l"(gaddr), "r"(saddr), "r"(bytes) : "memory");
}
__device__ __forceinline__ void bulk_commit() {
    asm volatile("cp.async.bulk.commit_group;\n" ::: "memory");
}
template <int N>
__device__ __forceinline__ void bulk_wait() {
    asm volatile("cp.async.bulk.wait_group %0;\n" :: "n"(N) : "memory");
}
__device__ __forceinline__ void fence_async_shared() {
    asm volatile("fence.proxy.async.shared::cta;\n" ::: "memory");
}

__device__ __forceinline__ void row_to_q(const float* __restrict__ v, float* __restrict__ o) {
    const float a = v[0], b = v[1], c = v[2], d = v[3], e = v[4], f = v[5];
    const float ab = a * b;
    const float ad = a * d;
    const float bdce = fmaf(b, d, c * e);
    o[0] = a * a;
    o[1] = ab;
    o[2] = ad;
    o[3] = ab;
    o[4] = fmaf(b, b, c * c);
    o[5] = bdce;
    o[6] = ad;
    o[7] = bdce;
    o[8] = fmaf(d, d, fmaf(e, e, f * f));
}

// Compute this warp's 64 rows of one tile: smem input slice -> smem output slice.
__device__ __forceinline__ void warp_compute(const float* __restrict__ sin_w,
                                             float* __restrict__ sout_w, int l)
{
#pragma unroll
    for (int j = 0; j < 2; j++) {
        const int r = l + 32 * j;
        float v[6], o[9];
#pragma unroll
        for (int k = 0; k < 6; k++) v[k] = sin_w[r * 6 + k];
        row_to_q(v, o);
#pragma unroll
        for (int k = 0; k < 9; k++) sout_w[r * 9 + k] = o[k];
    }
}

__global__ __launch_bounds__(TPB) void chol_to_cov_bulk(const float4* __restrict__ in4,
                                                        float* __restrict__ out,
                                                        int num_tiles)
{
    __shared__ float4 s_in[2][IN_F4];             // 12 KB
    __shared__ float  s_out[2][TPB / 32 * W_OUT_FLOATS];  // 2 x 9 KB = 18 KB

    const int t = threadIdx.x;
    const int w = t >> 5;
    const int l = t & 31;

    const int tile0 = blockIdx.x * 2;
    const int tile1 = tile0 + 1;
    const bool has1 = (tile1 < num_tiles);

    // Issue this warp's input slices: tile0 -> group0, tile1 -> group1.
    {
        const float4* ip0 = in4 + (size_t)tile0 * IN_F4 + w * W_IN;
        uint32_t sb0 = (uint32_t)__cvta_generic_to_shared(&s_in[0][w * W_IN]);
#pragma unroll
        for (int k = 0; k < 3; k++)
            cp_async16(sb0 + (l + 32 * k) * 16u, ip0 + l + 32 * k);
        cp_commit();
        if (has1) {
            const float4* ip1 = in4 + (size_t)tile1 * IN_F4 + w * W_IN;
            uint32_t sb1 = (uint32_t)__cvta_generic_to_shared(&s_in[1][w * W_IN]);
#pragma unroll
            for (int k = 0; k < 3; k++)
                cp_async16(sb1 + (l + 32 * k) * 16u, ip1 + l + 32 * k);
            cp_commit();
        }
    }

    // ---- Tile 0 ----
    {
        if (has1) cp_wait<1>(); else cp_wait<0>();
        __syncwarp();
        float* sout_w = &s_out[0][w * W_OUT_FLOATS];
        warp_compute(reinterpret_cast<const float*>(&s_in[0][w * W_IN]), sout_w, l);
        fence_async_shared();      // make this lane's STS visible to async proxy
        __syncwarp();              // all lanes' data + fences done before issue
        if (l == 0) {
            bulk_store(out + (size_t)tile0 * (ROWS_PB * 9) + w * W_OUT_FLOATS,
                       (uint32_t)__cvta_generic_to_shared(sout_w), W_OUT_BYTES);
            bulk_commit();
        }
    }

    // ---- Tile 1 ----
    if (has1) {
        cp_wait<0>();
        __syncwarp();
        // Double-buffered s_out: tile0's bulk store may still be in flight.
        float* sout_w = &s_out[1][w * W_OUT_FLOATS];
        warp_compute(reinterpret_cast<const float*>(&s_in[1][w * W_IN]), sout_w, l);
        fence_async_shared();
        __syncwarp();
        if (l == 0) {
            bulk_store(out + (size_t)tile1 * (ROWS_PB * 9) + w * W_OUT_FLOATS,
                       (uint32_t)__cvta_generic_to_shared(sout_w), W_OUT_BYTES);
            bulk_commit();
        }
    }
    // No final bulk_wait: async-proxy stores are guaranteed to complete
    // before kernel completion; smem lifetime ends only at block exit, after
    // the bulk engine has consumed it (bulk group tracks the read).
    bulk_wait<0>();  // conservative: ensure smem reads by bulk engine finished
}

// Scalar tail for the (< ROWS_PB) remainder rows.
__global__ void chol_to_cov_tail(const float* __restrict__ in,
                                 float* __restrict__ out,
                                 int start_row, int n_rows)
{
    const int r = start_row + blockIdx.x * blockDim.x + threadIdx.x;
    if (r >= n_rows) return;
    float v[6], o[9];
#pragma unroll
    for (int k = 0; k < 6; k++) v[k] = in[(size_t)r * 6 + k];
    row_to_q(v, o);
#pragma unroll
    for (int k = 0; k < 9; k++) out[(size_t)r * 9 + k] = o[k];
}

extern "C" void kernel_launch(void* const* d_in, const int* in_sizes, int n_in,
                              void* d_out, int out_size)
{
    const float* in = (const float*)d_in[0];
    float* out = (float*)d_out;
    const int n_rows = in_sizes[0] / 6;

    const int num_tiles = n_rows / ROWS_PB;
    if (num_tiles > 0) {
        const int blocks = (num_tiles + 1) / 2;
        chol_to_cov_bulk<<<blocks, TPB>>>((const float4*)in, out, num_tiles);
    }
    const int done = num_tiles * ROWS_PB;
    if (done < n_rows) {
        const int rem = n_rows - done;
        chol_to_cov_tail<<<(rem + 127) / 128, 128>>>(in, out, done, n_rows);
    }
}

// round 9
// speedup vs baseline: 1.0285x; 1.0214x over previous
#include <cuda_runtime.h>
#include <cstdint>

// Q = L @ L^T, L lower-triangular 3x3 from packed [a,b,c,d,e,f]:
//   Q00=a*a  Q01=a*b      Q02=a*d
//   Q10=a*b  Q11=b*b+c*c  Q12=b*d+c*e
//   Q20=a*d  Q21=b*d+c*e  Q22=d*d+e*e+f*f
//
// 2-tile pipeline with ONE BLOCK-WIDE 18KB ASYNC BULK STORE.
// Loads: cp.async.cg per lane (3x16B per tile per warp slice), 2 commit
// groups, warp-autonomous compute into a single contiguous smem output
// region covering both tiles (block output = 18432B contiguous in gmem).
// After both tiles are computed, one elected thread issues a single
// cp.async.bulk covering the whole block output, giving DRAM large
// strictly-sequential write bursts (fewer R/W turnarounds) instead of
// 8 x 2304B interleaved ops.

#define TPB 128
#define ROWS_PB 256
#define IN_F4 (ROWS_PB * 6 / 4)      // 384 f4/tile ; per warp: 96 (3/lane)
#define TILE_OUT_FLOATS (ROWS_PB * 9)  // 2304 floats = 9216 B
#define W_IN 96
#define W_ROWS 64
#define W_OUT_FLOATS (W_ROWS * 9)    // 576 floats

__device__ __forceinline__ void cp_async16(uint32_t saddr, const void* gaddr) {
    asm volatile("cp.async.cg.shared.global [%0], [%1], 16;\n" :: "r"(saddr), "l"(gaddr));
}
__device__ __forceinline__ void cp_commit() {
    asm volatile("cp.async.commit_group;\n" ::: "memory");
}
template <int N>
__device__ __forceinline__ void cp_wait() {
    asm volatile("cp.async.wait_group %0;\n" :: "n"(N) : "memory");
}

// Async bulk store: smem (shared::cta) -> gmem, tracked by bulk groups.
__device__ __forceinline__ void bulk_store(void* gaddr, uint32_t saddr, uint32_t bytes) {
    asm volatile("cp.async.bulk.global.shared::cta.bulk_group [%0], [%1], %2;\n"
                 :: "l"(gaddr), "r"(saddr), "r"(bytes) : "memory");
}
__device__ __forceinline__ void bulk_commit() {
    asm volatile("cp.async.bulk.commit_group;\n" ::: "memory");
}
template <int N>
__device__ __forceinline__ void bulk_wait() {
    asm volatile("cp.async.bulk.wait_group %0;\n" :: "n"(N) : "memory");
}
__device__ __forceinline__ void fence_async_shared() {
    asm volatile("fence.proxy.async.shared::cta;\n" ::: "memory");
}

__device__ __forceinline__ void row_to_q(const float* __restrict__ v, float* __restrict__ o) {
    const float a = v[0], b = v[1], c = v[2], d = v[3], e = v[4], f = v[5];
    const float ab = a * b;
    const float ad = a * d;
    const float bdce = fmaf(b, d, c * e);
    o[0] = a * a;
    o[1] = ab;
    o[2] = ad;
    o[3] = ab;
    o[4] = fmaf(b, b, c * c);
    o[5] = bdce;
    o[6] = ad;
    o[7] = bdce;
    o[8] = fmaf(d, d, fmaf(e, e, f * f));
}

// Compute this warp's 64 rows of one tile: smem input slice -> smem output slice.
__device__ __forceinline__ void warp_compute(const float* __restrict__ sin_w,
                                             float* __restrict__ sout_w, int l)
{
#pragma unroll
    for (int j = 0; j < 2; j++) {
        const int r = l + 32 * j;
        float v[6], o[9];
#pragma unroll
        for (int k = 0; k < 6; k++) v[k] = sin_w[r * 6 + k];
        row_to_q(v, o);
#pragma unroll
        for (int k = 0; k < 9; k++) sout_w[r * 9 + k] = o[k];
    }
}

__global__ __launch_bounds__(TPB) void chol_to_cov_blockbulk(const float4* __restrict__ in4,
                                                             float* __restrict__ out,
                                                             int num_tiles)
{
    __shared__ float4 s_in[2][IN_F4];              // 12 KB
    __shared__ float  s_out[2 * TILE_OUT_FLOATS];  // 18 KB, contiguous both tiles

    const int t = threadIdx.x;
    const int w = t >> 5;
    const int l = t & 31;

    const int tile0 = blockIdx.x * 2;
    const int tile1 = tile0 + 1;
    const bool has1 = (tile1 < num_tiles);

    // Issue this warp's input slices: tile0 -> group0, tile1 -> group1.
    {
        const float4* ip0 = in4 + (size_t)tile0 * IN_F4 + w * W_IN;
        uint32_t sb0 = (uint32_t)__cvta_generic_to_shared(&s_in[0][w * W_IN]);
#pragma unroll
        for (int k = 0; k < 3; k++)
            cp_async16(sb0 + (l + 32 * k) * 16u, ip0 + l + 32 * k);
        cp_commit();
        if (has1) {
            const float4* ip1 = in4 + (size_t)tile1 * IN_F4 + w * W_IN;
            uint32_t sb1 = (uint32_t)__cvta_generic_to_shared(&s_in[1][w * W_IN]);
#pragma unroll
            for (int k = 0; k < 3; k++)
                cp_async16(sb1 + (l + 32 * k) * 16u, ip1 + l + 32 * k);
            cp_commit();
        }
    }

    // ---- Tile 0 compute ----
    if (has1) cp_wait<1>(); else cp_wait<0>();
    __syncwarp();
    warp_compute(reinterpret_cast<const float*>(&s_in[0][w * W_IN]),
                 &s_out[w * W_OUT_FLOATS], l);

    // ---- Tile 1 compute ----
    if (has1) {
        cp_wait<0>();
        __syncwarp();
        warp_compute(reinterpret_cast<const float*>(&s_in[1][w * W_IN]),
                     &s_out[TILE_OUT_FLOATS + w * W_OUT_FLOATS], l);
    }

    // Make all STS visible to the async proxy, then one thread ships the
    // whole block output as a single large sequential bulk store.
    fence_async_shared();
    __syncthreads();
    if (t == 0) {
        const uint32_t bytes = has1 ? 2 * TILE_OUT_FLOATS * 4 : TILE_OUT_FLOATS * 4;
        bulk_store(out + (size_t)tile0 * TILE_OUT_FLOATS,
                   (uint32_t)__cvta_generic_to_shared(&s_out[0]), bytes);
        bulk_commit();
        bulk_wait<0>();  // keep smem alive until the bulk engine has read it
    }
}

// Scalar tail for the (< ROWS_PB) remainder rows.
__global__ void chol_to_cov_tail(const float* __restrict__ in,
                                 float* __restrict__ out,
                                 int start_row, int n_rows)
{
    const int r = start_row + blockIdx.x * blockDim.x + threadIdx.x;
    if (r >= n_rows) return;
    float v[6], o[9];
#pragma unroll
    for (int k = 0; k < 6; k++) v[k] = in[(size_t)r * 6 + k];
    row_to_q(v, o);
#pragma unroll
    for (int k = 0; k < 9; k++) out[(size_t)r * 9 + k] = o[k];
}

extern "C" void kernel_launch(void* const* d_in, const int* in_sizes, int n_in,
                              void* d_out, int out_size)
{
    const float* in = (const float*)d_in[0];
    float* out = (float*)d_out;
    const int n_rows = in_sizes[0] / 6;

    const int num_tiles = n_rows / ROWS_PB;
    if (num_tiles > 0) {
        const int blocks = (num_tiles + 1) / 2;
        chol_to_cov_blockbulk<<<blocks, TPB>>>((const float4*)in, out, num_tiles);
    }
    const int done = num_tiles * ROWS_PB;
    if (done < n_rows) {
        const int rem = n_rows - done;
        chol_to_cov_tail<<<(rem + 127) / 128, 128>>>(in, out, done, n_rows);
    }
}